// round 14
// baseline (speedup 1.0000x reference)
#include <cuda_runtime.h>
#include <cuda_fp16.h>
#include <stdint.h>

// ---------------------------------------------------------------------------
// Bidirectional GRU w/ predictor feedback. B=128, T=1024, H=512.
// 2 dirs x 4 groups x 16 CTAs; group g owns batches [32g,32g+32), CTA c owns
// hidden cols [32c,32c+32). C[32b x 128n] = h_g[32x512] @ Wc[128x512]^T via
// mma m16n8k16 fp16.
// R14: 8 MMA warps (m-split: warp w owns m-tile w>>2, n-group w&3 of each of
// R/Z/N/P) -> 2 MMA warps per SMSP, halved per-warp LDSM/HMMA chains,
// in-register gates kept. Single-pass K loop (A read once). A staged in two
// K-halves by 4 staging warps so half-1 load latency hides under half-0 MMA.
// ---------------------------------------------------------------------------

namespace {
constexpr int kT = 1024;
constexpr int kThreads = 384;
constexpr int kRowB = 1040;  // bytes per 512-fp16 row (+16B): 260w = 4 mod 32

// SMEM layout (bytes)
constexpr int kW = 0;               // 128 x 1040 = 133120
constexpr int kA = 133120;          // 32 x 1040  = 33280  (ends 166400)
constexpr int kSpp = 166400;        // 8 x 17 f32 = 544    (ends 166944)
constexpr int kSxin = 166944;       // 32 f32     = 128    (ends 167072)
constexpr int kSb = 167072;         // 384 f32    = 1536   (ends 168608)
constexpr int kSmemBytes = 169984;  // > 114KB -> 1 CTA/SM
}  // namespace

// Device-global scratch (no allocation allowed).
__device__ __align__(16) __half g_h[2][2][128][512];  // [dir][buf][b][k]
__device__ float g_spart[2][4][32][16];               // [dir][grp][b][cta]
__device__ unsigned int g_hcnt[2][4][32];             // per-group h counters
__device__ unsigned int g_scnt[2][4][32];             // per-group spart cnts
__device__ int g_mask_mode;                           // 0=u8, 1=i32, 2=f32

__device__ __forceinline__ float sigmoid_fast(float v) {
  return __fdividef(1.f, 1.f + __expf(-v));
}
__device__ __forceinline__ float tanh_fast(float v) {
  return 1.f - __fdividef(2.f, 1.f + __expf(2.f * v));
}
__device__ __forceinline__ uint32_t smem_u32(const void* p) {
  uint32_t a;
  asm("{ .reg .u64 t; cvta.to.shared.u64 t, %1; cvt.u32.u64 %0, t; }"
      : "=r"(a) : "l"(p));
  return a;
}
__device__ __forceinline__ void mma16816(float* d, uint32_t a0, uint32_t a1,
                                         uint32_t a2, uint32_t a3, uint32_t b0,
                                         uint32_t b1) {
  asm volatile(
      "mma.sync.aligned.m16n8k16.row.col.f32.f16.f16.f32 "
      "{%0,%1,%2,%3},{%4,%5,%6,%7},{%8,%9},{%0,%1,%2,%3};"
      : "+f"(d[0]), "+f"(d[1]), "+f"(d[2]), "+f"(d[3])
      : "r"(a0), "r"(a1), "r"(a2), "r"(a3), "r"(b0), "r"(b1));
}
#define LDM4(r, addr)                                                  \
  asm volatile(                                                        \
      "ldmatrix.sync.aligned.m8n8.x4.shared.b16 {%0,%1,%2,%3}, [%4];"  \
      : "=r"((r)[0]), "=r"((r)[1]), "=r"((r)[2]), "=r"((r)[3])         \
      : "r"(addr))
#define LDM2(r, addr)                                            \
  asm volatile(                                                  \
      "ldmatrix.sync.aligned.m8n8.x2.shared.b16 {%0,%1}, [%2];"  \
      : "=r"((r)[0]), "=r"((r)[1])                               \
      : "r"(addr))

__device__ __forceinline__ void bar_sync(int id, int cnt) {
  asm volatile("bar.sync %0, %1;" ::"r"(id), "r"(cnt) : "memory");
}
__device__ __forceinline__ void bar_arrive(int id, int cnt) {
  asm volatile("bar.arrive %0, %1;" ::"r"(id), "r"(cnt) : "memory");
}
__device__ __forceinline__ unsigned int poll_ge(const unsigned int* fp,
                                                unsigned int need) {
  unsigned int v;
  do {
    asm volatile("ld.acquire.gpu.u32 %0, [%1];" : "=r"(v) : "l"(fp) : "memory");
  } while ((int)(v - need) < 0);
  return v;
}
__device__ __forceinline__ void cnt_bump(unsigned int* cp) {
  asm volatile("fence.acq_rel.gpu;" ::: "memory");
  asm volatile("red.release.gpu.global.add.u32 [%0], 1;" ::"l"(cp) : "memory");
}

__global__ void init_kernel(const void* __restrict__ mask) {
  int idx = blockIdx.x * blockDim.x + threadIdx.x;  // 65536 threads
  if (idx < 32768)  // g_h = 512KB = 32768 uint4
    reinterpret_cast<uint4*>(&g_h[0][0][0][0])[idx] = make_uint4(0, 0, 0, 0);
  if (idx < 256) {
    (&g_hcnt[0][0][0])[idx] = 0u;
    (&g_scnt[0][0][0])[idx] = 0u;
  }
  if (idx == 0) {
    const int* i32 = (const int*)mask;
    const float* f32 = (const float*)mask;
    bool is_i32 = true, is_f32 = true;
    for (int i = 0; i < 64; ++i) {
      int v = i32[i];
      if (v != 0 && v != 1) is_i32 = false;
      float f = f32[i];
      if (!(f == 0.f || f == 1.f)) is_f32 = false;
    }
    g_mask_mode = is_i32 ? 1 : (is_f32 ? 2 : 0);
  }
}

__global__ void __launch_bounds__(kThreads, 1)
bidgru_kernel(const float* __restrict__ x, const void* __restrict__ mask,
              const float* __restrict__ wf_ih, const float* __restrict__ wf_hh,
              const float* __restrict__ bf_ih, const float* __restrict__ bf_hh,
              const float* __restrict__ wb_ih, const float* __restrict__ wb_hh,
              const float* __restrict__ bb_ih, const float* __restrict__ bb_hh,
              const float* __restrict__ p_w1, const float* __restrict__ p_b1,
              const float* __restrict__ p_w2, const float* __restrict__ p_b2,
              float* __restrict__ out) {
  extern __shared__ __align__(16) char smem_c[];
  const uint32_t smem_base = smem_u32(smem_c);
  float* sb = reinterpret_cast<float*>(smem_c + kSb);
  float* spp = reinterpret_cast<float*>(smem_c + kSpp);
  float* sxin = reinterpret_cast<float*>(smem_c + kSxin);

  const int tid = threadIdx.x;
  const int wid = tid >> 5;
  const int lane = tid & 31;
  const int d = blockIdx.x >> 6;        // direction
  const int g = (blockIdx.x >> 4) & 3;  // batch group
  const int c = blockIdx.x & 15;        // column CTA within group
  const int j0c = c * 32;
  const int b0g = g * 32;

  const float* w_hh = d ? wb_hh : wf_hh;
  const float* w_ih = d ? wb_ih : wf_ih;
  const float* b_hh = d ? bb_hh : bf_hh;
  const float* b_ih = d ? bb_ih : bf_ih;
  const int mmode = g_mask_mode;

  // ---- one-time W staging: fp32 -> fp16, 128 rows x 512, stride 1040B ----
  // rows 0..95: w_hh rows (r>>5)*512 + j0c + (r&31); rows 96..127: p_w1.
  for (int i = tid; i < 128 * 512; i += kThreads) {
    int r = i >> 9, k = i & 511;
    float v = (r < 96) ? w_hh[((r >> 5) * 512 + j0c + (r & 31)) * 512 + k]
                       : p_w1[(j0c + (r - 96)) * 512 + k];
    *reinterpret_cast<__half*>(smem_c + kW + r * kRowB + k * 2) =
        __float2half_rn(v);
  }
  if (tid < 96) {
    int gt = tid >> 5, jc = tid & 31;
    sb[tid] = b_hh[gt * 512 + j0c + jc];
    sb[96 + tid] = b_ih[gt * 512 + j0c + jc];
    sb[192 + tid] = w_ih[gt * 512 + j0c + jc];
  } else if (tid < 128) {
    int jc = tid - 96;
    sb[288 + jc] = p_b1[j0c + jc];
    sb[320 + jc] = p_w2[j0c + jc];
  } else if (tid == 128) {
    sb[352] = p_b2[0];
  }
  __syncthreads();

  const bool is_mma = tid < 256;
  const int r0q = lane >> 2, cq = lane & 3;
  const int md = lane >> 3, mr = lane & 7;
  const uint32_t a_off =
      (uint32_t)(((md & 1) * 8 + mr) * kRowB + (md >> 1) * 16);
  const uint32_t b2_off =
      (uint32_t)((lane & 7) * kRowB + ((lane >> 3) & 1) * 16);

  // MMA geometry: warp w (0-7): m-tile mt = w>>2, n-group jw = w&3.
  const int mt = wid >> 2, jw = wid & 3;

  // staging geometry (tid in [256,384)): warps 8-11; half0 = warps 8,9.
  const int half = (tid - 256) >> 6;       // 0 or 1
  const int th = (tid - 256) & 63;         // 0..63 within half

  // h state in MMA-warp registers: thread owns b = mt*16 + r0q (+8),
  // j = 8*jw + 2*cq (+1).  hreg[2*halfb + u]
  float hreg[4] = {0.f, 0.f, 0.f, 0.f};

  unsigned int* hcnt = &g_hcnt[d][g][0];
  unsigned int* scnt = &g_scnt[d][g][0];

  int cur = 0;

  for (int t = 0; t < kT; ++t) {
    const int pos = d ? (kT - 1 - t) : t;
    const int nxt = cur ^ 1;

    if (is_mma) {
      // ================= MMA warps 0-7 =================
      const uint32_t ab = smem_base + kA + (uint32_t)(mt * 16) * kRowB;
      const uint32_t wR = smem_base + kW + (uint32_t)(8 * jw) * kRowB;
      const uint32_t wZ = wR + 32u * kRowB;
      const uint32_t wN = wR + 64u * kRowB;
      const uint32_t wP = wR + 96u * kRowB;

      float accR[4] = {0.f, 0.f, 0.f, 0.f};
      float accZ[4] = {0.f, 0.f, 0.f, 0.f};
      float accN[4] = {0.f, 0.f, 0.f, 0.f};
      float accP[4] = {0.f, 0.f, 0.f, 0.f};

      bar_sync(2, 320);  // A half0 staged
#pragma unroll 4
      for (int kg = 0; kg < 16; ++kg) {
        uint32_t ah[4];
        LDM4(ah, ab + a_off + (uint32_t)(kg * 32));
        uint32_t br2[2], bz2[2], bn2[2], bp2[2];
        LDM2(br2, wR + b2_off + (uint32_t)(kg * 32));
        LDM2(bz2, wZ + b2_off + (uint32_t)(kg * 32));
        LDM2(bn2, wN + b2_off + (uint32_t)(kg * 32));
        LDM2(bp2, wP + b2_off + (uint32_t)(kg * 32));
        mma16816(accR, ah[0], ah[1], ah[2], ah[3], br2[0], br2[1]);
        mma16816(accZ, ah[0], ah[1], ah[2], ah[3], bz2[0], bz2[1]);
        mma16816(accN, ah[0], ah[1], ah[2], ah[3], bn2[0], bn2[1]);
        mma16816(accP, ah[0], ah[1], ah[2], ah[3], bp2[0], bp2[1]);
      }
      bar_sync(3, 320);  // A half1 staged
#pragma unroll 4
      for (int kg = 16; kg < 32; ++kg) {
        uint32_t ah[4];
        LDM4(ah, ab + a_off + (uint32_t)(kg * 32));
        uint32_t br2[2], bz2[2], bn2[2], bp2[2];
        LDM2(br2, wR + b2_off + (uint32_t)(kg * 32));
        LDM2(bz2, wZ + b2_off + (uint32_t)(kg * 32));
        LDM2(bn2, wN + b2_off + (uint32_t)(kg * 32));
        LDM2(bp2, wP + b2_off + (uint32_t)(kg * 32));
        mma16816(accR, ah[0], ah[1], ah[2], ah[3], br2[0], br2[1]);
        mma16816(accZ, ah[0], ah[1], ah[2], ah[3], bz2[0], bz2[1]);
        mma16816(accN, ah[0], ah[1], ah[2], ah[3], bn2[0], bn2[1]);
        mma16816(accP, ah[0], ah[1], ah[2], ah[3], bp2[0], bp2[1]);
      }

      // ---- spart partials: reduce accP over this warp's 8 pred cols ----
      {
        const int pr = 8 * jw + 2 * cq;
        const float b1a = sb[288 + pr], b1b = sb[288 + pr + 1];
        const float w2a = sb[320 + pr], w2b = sb[320 + pr + 1];
        float glo = fmaxf(accP[0] + b1a, 0.f) * w2a +
                    fmaxf(accP[1] + b1b, 0.f) * w2b;
        float ghi = fmaxf(accP[2] + b1a, 0.f) * w2a +
                    fmaxf(accP[3] + b1b, 0.f) * w2b;
        glo += __shfl_xor_sync(0xFFFFFFFFu, glo, 1);
        glo += __shfl_xor_sync(0xFFFFFFFFu, glo, 2);
        ghi += __shfl_xor_sync(0xFFFFFFFFu, ghi, 1);
        ghi += __shfl_xor_sync(0xFFFFFFFFu, ghi, 2);
        if (cq == 0) {
          spp[wid * 17 + r0q] = glo;
          spp[wid * 17 + r0q + 8] = ghi;
        }
      }
      bar_sync(6, 256);
      if (wid == 0) {  // combine 4 jw-partials per b, publish spart
        const int mb = lane >> 4, bl = lane & 15;
        const int w0 = mb * 4;
        float v = spp[w0 * 17 + bl] + spp[(w0 + 1) * 17 + bl] +
                  spp[(w0 + 2) * 17 + bl] + spp[(w0 + 3) * 17 + bl];
        __stcg(&g_spart[d][g][lane][c], v);
        __syncwarp();
        if (lane == 0) cnt_bump(scnt);
      }

      bar_sync(11, 288);  // sxin ready

      // ---- gates + h update in-register ----
      const int j = 8 * jw + 2 * cq;
      const float sbr0 = sb[j], sbr1 = sb[j + 1];
      const float sbz0 = sb[32 + j], sbz1 = sb[32 + j + 1];
      const float sbn0 = sb[64 + j], sbn1 = sb[64 + j + 1];
      const float bir0 = sb[96 + j], bir1 = sb[96 + j + 1];
      const float biz0 = sb[96 + 32 + j], biz1 = sb[96 + 32 + j + 1];
      const float bin0 = sb[96 + 64 + j], bin1 = sb[96 + 64 + j + 1];
      const float wir0 = sb[192 + j], wir1 = sb[192 + j + 1];
      const float wiz0 = sb[192 + 32 + j], wiz1 = sb[192 + 32 + j + 1];
      const float win0 = sb[192 + 64 + j], win1 = sb[192 + 64 + j + 1];

      float onew[4];
#pragma unroll
      for (int hb = 0; hb < 2; ++hb) {
        const float xin = sxin[mt * 16 + r0q + 8 * hb];
#pragma unroll
        for (int u = 0; u < 2; ++u) {
          const int idx = 2 * hb + u;
          float gr = accR[idx] + (u ? sbr1 : sbr0) +
                     fmaf(xin, u ? wir1 : wir0, u ? bir1 : bir0);
          float gz = accZ[idx] + (u ? sbz1 : sbz0) +
                     fmaf(xin, u ? wiz1 : wiz0, u ? biz1 : biz0);
          float ghn = accN[idx] + (u ? sbn1 : sbn0);
          float gin = fmaf(xin, u ? win1 : win0, u ? bin1 : bin0);
          float r = sigmoid_fast(gr);
          float z = sigmoid_fast(gz);
          float n = tanh_fast(fmaf(r, ghn, gin));
          float hnew = fmaf(z, hreg[idx] - n, n);
          hreg[idx] = hnew;
          onew[idx] = hnew;
        }
      }
      // publish h' (fp16, one uint32 per (b, j-pair))
#pragma unroll
      for (int hb = 0; hb < 2; ++hb) {
        const int b_glob = b0g + mt * 16 + r0q + 8 * hb;
        uint32_t hv =
            (uint32_t)__half_as_ushort(__float2half_rn(onew[2 * hb])) |
            ((uint32_t)__half_as_ushort(__float2half_rn(onew[2 * hb + 1]))
             << 16);
        __stcg(reinterpret_cast<uint32_t*>(&g_h[d][nxt][b_glob][j0c + j]), hv);
      }
      bar_sync(9, 256);  // all h' stores done
      if (tid == 0) cnt_bump(hcnt);
      // out stores (after bump; off the critical path)
#pragma unroll
      for (int hb = 0; hb < 2; ++hb) {
        const int b_glob = b0g + mt * 16 + r0q + 8 * hb;
        *reinterpret_cast<float2*>(out + ((size_t)b_glob << 20) +
                                   ((size_t)pos << 10) + (d << 9) + j0c + j) =
            make_float2(onew[2 * hb], onew[2 * hb + 1]);
      }
    } else {
      // ================= staging warps 8-11 =================
      float xv = 0.f;
      bool m = false;
      if (wid == 8) {  // prefetch for sxin
        const int b_glob = b0g + lane;
        xv = __ldg(&x[(size_t)b_glob * kT + pos]);
        const size_t midx = (size_t)b_glob * kT + pos;
        if (mmode == 1)
          m = ((const int*)mask)[midx] != 0;
        else if (mmode == 2)
          m = ((const float*)mask)[midx] != 0.f;
        else
          m = ((const uint8_t*)mask)[midx] != 0;
      }

      if (t > 0) {
        if (tid == 256) poll_ge(hcnt, (unsigned)(16 * t));
        bar_sync(5, 128);
      }
      {
        const uint4* hb4 = reinterpret_cast<const uint4*>(&g_h[d][cur][0][0]);
#pragma unroll
        for (int it = 0; it < 16; ++it) {
          const int task = it * 64 + th;  // 0..1023 within half
          const int b = task >> 5;        // 0..31
          const int q = task & 31;
          const int k16 = half * 32 + q;
          uint4 v = __ldcg(hb4 + (b0g + b) * 64 + k16);
          *reinterpret_cast<uint4*>(smem_c + kA + b * kRowB + k16 * 16) = v;
        }
      }
      bar_arrive(2 + half, 320);  // half staged

      if (wid == 8) {  // sxin[32]
        if (lane == 0) poll_ge(scnt, (unsigned)(16 * (t + 1)));
        __syncwarp();
        float a = 0.f;
        const float4* pp =
            reinterpret_cast<const float4*>(&g_spart[d][g][lane][0]);
#pragma unroll
        for (int q = 0; q < 4; ++q) {
          float4 v = __ldcg(pp + q);
          a += v.x + v.y + v.z + v.w;
        }
        const float scal = tanh_fast(a + sb[352]);
        sxin[lane] = m ? scal : xv;
        bar_arrive(11, 288);
      }
    }
    cur = nxt;
  }
}

extern "C" void kernel_launch(void* const* d_in, const int* in_sizes, int n_in,
                              void* d_out, int out_size) {
  const float* x = (const float*)d_in[0];
  const void* mask = (const void*)d_in[1];
  const float* wf_ih = (const float*)d_in[2];
  const float* wf_hh = (const float*)d_in[3];
  const float* bf_ih = (const float*)d_in[4];
  const float* bf_hh = (const float*)d_in[5];
  const float* wb_ih = (const float*)d_in[6];
  const float* wb_hh = (const float*)d_in[7];
  const float* bb_ih = (const float*)d_in[8];
  const float* bb_hh = (const float*)d_in[9];
  const float* p_w1 = (const float*)d_in[10];
  const float* p_b1 = (const float*)d_in[11];
  const float* p_w2 = (const float*)d_in[12];
  const float* p_b2 = (const float*)d_in[13];
  float* out = (float*)d_out;

  (void)in_sizes;
  (void)n_in;
  (void)out_size;

  cudaFuncSetAttribute(bidgru_kernel, cudaFuncAttributeMaxDynamicSharedMemorySize,
                       kSmemBytes);
  init_kernel<<<256, 256>>>(mask);
  bidgru_kernel<<<128, kThreads, kSmemBytes>>>(x, mask, wf_ih, wf_hh, bf_ih,
                                               bf_hh, wb_ih, wb_hh, bb_ih, bb_hh,
                                               p_w1, p_b1, p_w2, p_b2, out);
}